// round 8
// baseline (speedup 1.0000x reference)
#include <cuda_runtime.h>
#include <cuda_bf16.h>
#include <stdint.h>

#define NN 100000
#define NN_PAD 100096
#define NE 1600000
#define IN_DIM 128
#define HID_DIM 256
#define OUT_DIM 64

// ---------------- device scratch ----------------
__device__ __align__(16) float g_norm_src[NN_PAD];
__device__ __align__(16) float g_norm_dst[NN_PAD];
__device__ __align__(16) float g_xagg[(size_t)NN_PAD * IN_DIM];
__device__ __align__(16) __nv_bfloat16 g_w1t_hi[HID_DIM * IN_DIM];   // [n][k]
__device__ __align__(16) __nv_bfloat16 g_w1t_lo[HID_DIM * IN_DIM];
__device__ __align__(16) __nv_bfloat16 g_w2t_hi[OUT_DIM * HID_DIM];  // [n][k]
__device__ __align__(16) __nv_bfloat16 g_w2t_lo[OUT_DIM * HID_DIM];
__device__ __align__(16) __nv_bfloat16 g_hid_hi[(size_t)NN_PAD * HID_DIM];
__device__ __align__(16) __nv_bfloat16 g_hid_lo[(size_t)NN_PAD * HID_DIM];
__device__ __align__(16) float g_ypre[(size_t)NN * OUT_DIM];

__device__ __forceinline__ void split_bf16(float v, __nv_bfloat16& hi, __nv_bfloat16& lo) {
    hi = __float2bfloat16(v);
    lo = __float2bfloat16(v - __bfloat162float(hi));
}

#define MMA_BF16(d, a, b0, b1)                                                  \
    asm volatile("mma.sync.aligned.m16n8k16.row.col.f32.bf16.bf16.f32 "         \
                 "{%0,%1,%2,%3}, {%4,%5,%6,%7}, {%8,%9}, {%0,%1,%2,%3};"        \
                 : "+f"(d[0]), "+f"(d[1]), "+f"(d[2]), "+f"(d[3])               \
                 : "r"(a[0]), "r"(a[1]), "r"(a[2]), "r"(a[3]), "r"(b0), "r"(b1))

// ---------------- zero init ----------------
__global__ void k_zero(float4* __restrict__ dout4, int n_nodes) {
    int i = blockIdx.x * blockDim.x + threadIdx.x;
    int stride = gridDim.x * blockDim.x;
    const float4 z = make_float4(0.f, 0.f, 0.f, 0.f);
    const int nx4 = NN_PAD * (IN_DIM / 4);
    float4* xagg4 = reinterpret_cast<float4*>(g_xagg);
    for (int j = i; j < nx4; j += stride) xagg4[j] = z;
    const int no4 = n_nodes * (OUT_DIM / 4);
    for (int j = i; j < no4; j += stride) dout4[j] = z;
    for (int j = i; j < NN_PAD; j += stride) { g_norm_src[j] = 0.f; g_norm_dst[j] = 0.f; }
    const int hid_pad4 = (NN_PAD - NN) * (HID_DIM / 4);
    uint2* hh = reinterpret_cast<uint2*>(g_hid_hi + (size_t)NN * HID_DIM);
    uint2* hl = reinterpret_cast<uint2*>(g_hid_lo + (size_t)NN * HID_DIM);
    const uint2 z2 = make_uint2(0u, 0u);
    for (int j = i; j < hid_pad4; j += stride) { hh[j] = z2; hl[j] = z2; }
}

// ---------------- degrees ----------------
__global__ void k_degree(const int* __restrict__ src, const int* __restrict__ dst, int n_edges) {
    int i = blockIdx.x * blockDim.x + threadIdx.x;
    int stride = gridDim.x * blockDim.x;
    for (int e = i; e < n_edges; e += stride) {
        atomicAdd(&g_norm_src[src[e]], 1.0f);
        atomicAdd(&g_norm_dst[dst[e]], 1.0f);
    }
}

__global__ void k_norm(int n_nodes) {
    int i = blockIdx.x * blockDim.x + threadIdx.x;
    if (i < n_nodes) {
        g_norm_src[i] = rsqrtf(fmaxf(g_norm_src[i], 1.0f));
        g_norm_dst[i] = rsqrtf(fmaxf(g_norm_dst[i], 1.0f));
    }
}

// ---------------- pre-split weights (transposed [n][k]) ----------------
__global__ void k_prepw(const float* __restrict__ W1, const float* __restrict__ W2) {
    int i = blockIdx.x * blockDim.x + threadIdx.x;
    const int n1 = HID_DIM * IN_DIM;     // 32768
    const int n2 = OUT_DIM * HID_DIM;    // 16384
    if (i < n1) {
        int n = i / IN_DIM, k = i % IN_DIM;
        float v = W1[(size_t)k * HID_DIM + n];
        __nv_bfloat16 hi, lo;
        split_bf16(v, hi, lo);
        g_w1t_hi[i] = hi; g_w1t_lo[i] = lo;
    } else if (i < n1 + n2) {
        int j = i - n1;
        int n = j / HID_DIM, k = j % HID_DIM;
        float v = W2[(size_t)k * OUT_DIM + n];
        __nv_bfloat16 hi, lo;
        split_bf16(v, hi, lo);
        g_w2t_hi[j] = hi; g_w2t_lo[j] = lo;
    }
}

// ---------------- SpMM1: xagg[dst] += h[src]*norm_src[src], 4 edges/warp (R2) ----------------
__global__ void k_spmm1(const float* __restrict__ h,
                        const int* __restrict__ src, const int* __restrict__ dst,
                        int n_edges) {
    int w = (blockIdx.x * blockDim.x + threadIdx.x) >> 5;
    int lane = threadIdx.x & 31;
    int e0 = w * 4;
    if (e0 >= n_edges) return;
    int s[4], d[4];
    float ns[4];
    #pragma unroll
    for (int i = 0; i < 4; i++) {
        int e = min(e0 + i, n_edges - 1);
        s[i] = __ldg(&src[e]);
        d[i] = __ldg(&dst[e]);
    }
    #pragma unroll
    for (int i = 0; i < 4; i++) ns[i] = g_norm_src[s[i]];
    float4 v[4];
    #pragma unroll
    for (int i = 0; i < 4; i++)
        v[i] = reinterpret_cast<const float4*>(h + (size_t)s[i] * IN_DIM)[lane];
    #pragma unroll
    for (int i = 0; i < 4; i++) {
        if (e0 + i >= n_edges) break;
        float4 t = v[i];
        t.x *= ns[i]; t.y *= ns[i]; t.z *= ns[i]; t.w *= ns[i];
        float4* orow = reinterpret_cast<float4*>(g_xagg + (size_t)d[i] * IN_DIM);
        asm volatile("red.global.add.v4.f32 [%0], {%1,%2,%3,%4};"
                     :: "l"(orow + lane), "f"(t.x), "f"(t.y), "f"(t.z), "f"(t.w)
                     : "memory");
    }
}

// ================= GEMM1: BM=128, BN=128, BK=32, 512 threads =================
// hidden = relu((xagg*norm_dst) @ W1 + b1) * clip(p,0,1); split-bf16 store
#define G1_BM 128
#define G1_BN 128
#define G1_BK 32
#define KPAD 40

__global__ __launch_bounds__(512) void k_gemm1(const float* __restrict__ b1,
                                               const float* __restrict__ p,
                                               int n_nodes) {
    __shared__ __align__(16) __nv_bfloat16 As_hi[G1_BM * KPAD];
    __shared__ __align__(16) __nv_bfloat16 As_lo[G1_BM * KPAD];
    __shared__ __align__(16) __nv_bfloat16 Bs_hi[G1_BN * KPAD];
    __shared__ __align__(16) __nv_bfloat16 Bs_lo[G1_BN * KPAD];

    const int m0 = blockIdx.x * G1_BM;
    const int n0 = blockIdx.y * G1_BN;
    const int tid = threadIdx.x;
    const int lane = tid & 31;
    const int wid = tid >> 5;         // 0..15
    const int warp_m = wid & 3;       // 4 warps in M (32 rows each)
    const int warp_n = wid >> 2;      // 4 warps in N (32 cols each)

    float acc[2][4][4];
    #pragma unroll
    for (int i = 0; i < 2; i++)
        #pragma unroll
        for (int j = 0; j < 4; j++)
            #pragma unroll
            for (int q = 0; q < 4; q++) acc[i][j][q] = 0.f;

    for (int k0 = 0; k0 < IN_DIM; k0 += G1_BK) {
        // A tile: 128 rows x 32 k fp32 -> inline norm+split. 1024 float4, 2/thread.
        #pragma unroll
        for (int i = 0; i < 2; i++) {
            int idx = tid + i * 512;
            int row = idx >> 3;          // 0..127
            int kk = (idx & 7) * 4;      // 0..28
            int grow = m0 + row;
            float nd = g_norm_dst[grow];
            float4 v = *reinterpret_cast<const float4*>(&g_xagg[(size_t)grow * IN_DIM + k0 + kk]);
            v.x *= nd; v.y *= nd; v.z *= nd; v.w *= nd;
            __nv_bfloat16 h0, l0, h1, l1, h2, l2, h3, l3;
            split_bf16(v.x, h0, l0); split_bf16(v.y, h1, l1);
            split_bf16(v.z, h2, l2); split_bf16(v.w, h3, l3);
            *reinterpret_cast<__nv_bfloat162*>(&As_hi[row * KPAD + kk])     = __nv_bfloat162(h0, h1);
            *reinterpret_cast<__nv_bfloat162*>(&As_hi[row * KPAD + kk + 2]) = __nv_bfloat162(h2, h3);
            *reinterpret_cast<__nv_bfloat162*>(&As_lo[row * KPAD + kk])     = __nv_bfloat162(l0, l1);
            *reinterpret_cast<__nv_bfloat162*>(&As_lo[row * KPAD + kk + 2]) = __nv_bfloat162(l2, l3);
        }
        // B tile: 128 n x 32 k, pure uint4 copies (512 uint4 per array, 1/thread)
        {
            int n = tid >> 2;            // 0..127
            int q = tid & 3;             // 0..3
            uint4 vh = *reinterpret_cast<const uint4*>(&g_w1t_hi[(size_t)(n0 + n) * IN_DIM + k0 + 8 * q]);
            uint4 vl = *reinterpret_cast<const uint4*>(&g_w1t_lo[(size_t)(n0 + n) * IN_DIM + k0 + 8 * q]);
            *reinterpret_cast<uint4*>(&Bs_hi[n * KPAD + 8 * q]) = vh;
            *reinterpret_cast<uint4*>(&Bs_lo[n * KPAD + 8 * q]) = vl;
        }
        __syncthreads();

        #pragma unroll
        for (int ks = 0; ks < 2; ks++) {
            const int kc = ks * 16 + 2 * (lane & 3);
            uint32_t ah[2][4], al[2][4];
            #pragma unroll
            for (int i = 0; i < 2; i++) {
                int r = warp_m * 32 + i * 16 + (lane >> 2);
                ah[i][0] = *reinterpret_cast<uint32_t*>(&As_hi[r * KPAD + kc]);
                ah[i][1] = *reinterpret_cast<uint32_t*>(&As_hi[(r + 8) * KPAD + kc]);
                ah[i][2] = *reinterpret_cast<uint32_t*>(&As_hi[r * KPAD + kc + 8]);
                ah[i][3] = *reinterpret_cast<uint32_t*>(&As_hi[(r + 8) * KPAD + kc + 8]);
                al[i][0] = *reinterpret_cast<uint32_t*>(&As_lo[r * KPAD + kc]);
                al[i][1] = *reinterpret_cast<uint32_t*>(&As_lo[(r + 8) * KPAD + kc]);
                al[i][2] = *reinterpret_cast<uint32_t*>(&As_lo[r * KPAD + kc + 8]);
                al[i][3] = *reinterpret_cast<uint32_t*>(&As_lo[(r + 8) * KPAD + kc + 8]);
            }
            #pragma unroll
            for (int j = 0; j < 4; j++) {
                int c = warp_n * 32 + j * 8 + (lane >> 2);
                uint32_t bh0 = *reinterpret_cast<uint32_t*>(&Bs_hi[c * KPAD + kc]);
                uint32_t bh1 = *reinterpret_cast<uint32_t*>(&Bs_hi[c * KPAD + kc + 8]);
                uint32_t bl0 = *reinterpret_cast<uint32_t*>(&Bs_lo[c * KPAD + kc]);
                uint32_t bl1 = *reinterpret_cast<uint32_t*>(&Bs_lo[c * KPAD + kc + 8]);
                #pragma unroll
                for (int i = 0; i < 2; i++) {
                    MMA_BF16(acc[i][j], ah[i], bh0, bh1);
                    MMA_BF16(acc[i][j], ah[i], bl0, bl1);
                    MMA_BF16(acc[i][j], al[i], bh0, bh1);
                }
            }
        }
        __syncthreads();
    }

    // epilogue: bias + relu + p-scale, split store
    #pragma unroll
    for (int i = 0; i < 2; i++) {
        int r = warp_m * 32 + i * 16 + (lane >> 2);
        #pragma unroll
        for (int j = 0; j < 4; j++) {
            int c0 = n0 + warp_n * 32 + j * 8 + 2 * (lane & 3);
            float bb0 = b1[c0], bb1 = b1[c0 + 1];
            float p0 = fminf(fmaxf(p[c0], 0.f), 1.f);
            float p1 = fminf(fmaxf(p[c0 + 1], 0.f), 1.f);
            #pragma unroll
            for (int hrow = 0; hrow < 2; hrow++) {
                int grow = m0 + r + 8 * hrow;
                if (grow >= n_nodes) continue;
                float v0 = fmaxf(acc[i][j][2 * hrow + 0] + bb0, 0.f) * p0;
                float v1 = fmaxf(acc[i][j][2 * hrow + 1] + bb1, 0.f) * p1;
                __nv_bfloat16 h0, l0, h1, l1;
                split_bf16(v0, h0, l0);
                split_bf16(v1, h1, l1);
                *reinterpret_cast<__nv_bfloat162*>(&g_hid_hi[(size_t)grow * HID_DIM + c0]) = __nv_bfloat162(h0, h1);
                *reinterpret_cast<__nv_bfloat162*>(&g_hid_lo[(size_t)grow * HID_DIM + c0]) = __nv_bfloat162(l0, l1);
            }
        }
    }
}

// ================= GEMM2 (R7 config): BM=128, BN=64, BK=32, copy-only loads =================
#define BM 128
#define BN 64
#define BK 32

__global__ __launch_bounds__(256) void k_gemm2(int n_nodes) {
    __shared__ __align__(16) __nv_bfloat16 As_hi[BM * KPAD];
    __shared__ __align__(16) __nv_bfloat16 As_lo[BM * KPAD];
    __shared__ __align__(16) __nv_bfloat16 Bs_hi[BN * KPAD];
    __shared__ __align__(16) __nv_bfloat16 Bs_lo[BN * KPAD];

    const int m0 = blockIdx.x * BM;
    const int tid = threadIdx.x;
    const int lane = tid & 31;
    const int wid = tid >> 5;
    const int warp_m = wid >> 2;
    const int warp_n = wid & 3;

    float acc[4][2][4];
    #pragma unroll
    for (int i = 0; i < 4; i++)
        #pragma unroll
        for (int j = 0; j < 2; j++)
            #pragma unroll
            for (int q = 0; q < 4; q++) acc[i][j][q] = 0.f;

    for (int k0 = 0; k0 < HID_DIM; k0 += BK) {
        #pragma unroll
        for (int i = 0; i < 2; i++) {
            int idx = tid + 256 * i;
            int row = idx >> 2;
            int q = idx & 3;
            uint4 vh = *reinterpret_cast<const uint4*>(&g_hid_hi[(size_t)(m0 + row) * HID_DIM + k0 + 8 * q]);
            uint4 vl = *reinterpret_cast<const uint4*>(&g_hid_lo[(size_t)(m0 + row) * HID_DIM + k0 + 8 * q]);
            *reinterpret_cast<uint4*>(&As_hi[row * KPAD + 8 * q]) = vh;
            *reinterpret_cast<uint4*>(&As_lo[row * KPAD + 8 * q]) = vl;
        }
        {
            int n = tid >> 2;
            int q = tid & 3;
            uint4 vh = *reinterpret_cast<const uint4*>(&g_w2t_hi[(size_t)n * HID_DIM + k0 + 8 * q]);
            uint4 vl = *reinterpret_cast<const uint4*>(&g_w2t_lo[(size_t)n * HID_DIM + k0 + 8 * q]);
            *reinterpret_cast<uint4*>(&Bs_hi[n * KPAD + 8 * q]) = vh;
            *reinterpret_cast<uint4*>(&Bs_lo[n * KPAD + 8 * q]) = vl;
        }
        __syncthreads();

        #pragma unroll
        for (int ks = 0; ks < 2; ks++) {
            const int kc = ks * 16 + 2 * (lane & 3);
            uint32_t ah[4][4], al[4][4];
            #pragma unroll
            for (int i = 0; i < 4; i++) {
                int r = warp_m * 64 + i * 16 + (lane >> 2);
                ah[i][0] = *reinterpret_cast<uint32_t*>(&As_hi[r * KPAD + kc]);
                ah[i][1] = *reinterpret_cast<uint32_t*>(&As_hi[(r + 8) * KPAD + kc]);
                ah[i][2] = *reinterpret_cast<uint32_t*>(&As_hi[r * KPAD + kc + 8]);
                ah[i][3] = *reinterpret_cast<uint32_t*>(&As_hi[(r + 8) * KPAD + kc + 8]);
                al[i][0] = *reinterpret_cast<uint32_t*>(&As_lo[r * KPAD + kc]);
                al[i][1] = *reinterpret_cast<uint32_t*>(&As_lo[(r + 8) * KPAD + kc]);
                al[i][2] = *reinterpret_cast<uint32_t*>(&As_lo[r * KPAD + kc + 8]);
                al[i][3] = *reinterpret_cast<uint32_t*>(&As_lo[(r + 8) * KPAD + kc + 8]);
            }
            #pragma unroll
            for (int j = 0; j < 2; j++) {
                int c = warp_n * 16 + j * 8 + (lane >> 2);
                uint32_t bh0 = *reinterpret_cast<uint32_t*>(&Bs_hi[c * KPAD + kc]);
                uint32_t bh1 = *reinterpret_cast<uint32_t*>(&Bs_hi[c * KPAD + kc + 8]);
                uint32_t bl0 = *reinterpret_cast<uint32_t*>(&Bs_lo[c * KPAD + kc]);
                uint32_t bl1 = *reinterpret_cast<uint32_t*>(&Bs_lo[c * KPAD + kc + 8]);
                #pragma unroll
                for (int i = 0; i < 4; i++) {
                    MMA_BF16(acc[i][j], ah[i], bh0, bh1);
                    MMA_BF16(acc[i][j], ah[i], bl0, bl1);
                    MMA_BF16(acc[i][j], al[i], bh0, bh1);
                }
            }
        }
        __syncthreads();
    }

    #pragma unroll
    for (int i = 0; i < 4; i++) {
        int r = warp_m * 64 + i * 16 + (lane >> 2);
        #pragma unroll
        for (int j = 0; j < 2; j++) {
            int c0 = warp_n * 16 + j * 8 + 2 * (lane & 3);
            #pragma unroll
            for (int hrow = 0; hrow < 2; hrow++) {
                int grow = m0 + r + 8 * hrow;
                if (grow >= n_nodes) continue;
                float ns = g_norm_src[grow];
                float2 v;
                v.x = acc[i][j][2 * hrow + 0] * ns;
                v.y = acc[i][j][2 * hrow + 1] * ns;
                *reinterpret_cast<float2*>(&g_ypre[(size_t)grow * OUT_DIM + c0]) = v;
            }
        }
    }
}

// ---------------- SpMM2: out[dst] += ypre[src], 8 edges/warp (R2) ----------------
__global__ void k_spmm2(const int* __restrict__ src, const int* __restrict__ dst,
                        float* __restrict__ out, int n_edges) {
    int w = (blockIdx.x * blockDim.x + threadIdx.x) >> 5;
    int lane = threadIdx.x & 31;
    int half = lane >> 4;
    int l = lane & 15;
    int e0 = w * 8;
    if (e0 >= n_edges) return;
    int s[4], d[4];
    #pragma unroll
    for (int i = 0; i < 4; i++) {
        int e = min(e0 + 2 * i + half, n_edges - 1);
        s[i] = __ldg(&src[e]);
        d[i] = __ldg(&dst[e]);
    }
    float4 v[4];
    #pragma unroll
    for (int i = 0; i < 4; i++)
        v[i] = reinterpret_cast<const float4*>(g_ypre + (size_t)s[i] * OUT_DIM)[l];
    #pragma unroll
    for (int i = 0; i < 4; i++) {
        if (e0 + 2 * i + half >= n_edges) break;
        float4* orow = reinterpret_cast<float4*>(out + (size_t)d[i] * OUT_DIM);
        asm volatile("red.global.add.v4.f32 [%0], {%1,%2,%3,%4};"
                     :: "l"(orow + l), "f"(v[i].x), "f"(v[i].y), "f"(v[i].z), "f"(v[i].w)
                     : "memory");
    }
}

// ---------------- final: out = out * norm_dst[row] + b2[col] ----------------
__global__ void k_final(float* __restrict__ out, const float* __restrict__ b2, int n_nodes) {
    int i = blockIdx.x * blockDim.x + threadIdx.x;
    int total = n_nodes * (OUT_DIM / 4);
    if (i >= total) return;
    int row = i >> 4;
    int c4 = i & 15;
    float nd = g_norm_dst[row];
    float4 v = reinterpret_cast<float4*>(out)[i];
    const float4 bb = reinterpret_cast<const float4*>(b2)[c4];
    v.x = v.x * nd + bb.x;
    v.y = v.y * nd + bb.y;
    v.z = v.z * nd + bb.z;
    v.w = v.w * nd + bb.w;
    reinterpret_cast<float4*>(out)[i] = v;
}

// ---------------- launch ----------------
extern "C" void kernel_launch(void* const* d_in, const int* in_sizes, int n_in,
                              void* d_out, int out_size) {
    const float* h  = (const float*)d_in[0];
    const float* W1 = (const float*)d_in[1];
    const float* b1 = (const float*)d_in[2];
    const float* W2 = (const float*)d_in[3];
    const float* b2 = (const float*)d_in[4];
    const float* p  = (const float*)d_in[5];
    const int* src  = (const int*)d_in[6];
    const int* dst  = (const int*)d_in[7];

    const int n_nodes = in_sizes[0] / IN_DIM;   // 100000
    const int n_edges = in_sizes[6];            // 1600000
    float* out = (float*)d_out;

    k_zero<<<4096, 256>>>(reinterpret_cast<float4*>(out), n_nodes);
    k_prepw<<<(HID_DIM * IN_DIM + OUT_DIM * HID_DIM + 255) / 256, 256>>>(W1, W2);
    k_degree<<<(n_edges + 255) / 256, 256>>>(src, dst, n_edges);
    k_norm<<<(n_nodes + 255) / 256, 256>>>(n_nodes);

    // SpMM1: 4 edges per warp (R2 config)
    {
        int warps = (n_edges + 3) / 4;
        k_spmm1<<<(warps + 7) / 8, 256>>>(h, src, dst, n_edges);
    }
    // GEMM1: BM=128, BN=128, 512 threads, inline norm+split A, copy-only B
    {
        dim3 grid(NN_PAD / G1_BM, HID_DIM / G1_BN);   // 782 x 2
        k_gemm1<<<grid, 512>>>(b1, p, n_nodes);
    }
    // GEMM2 (copy-only loads)
    {
        dim3 grid(NN_PAD / BM, 1);                    // 782
        k_gemm2<<<grid, 256>>>(n_nodes);
    }
    // SpMM2: 8 edges per warp (R2 config)
    {
        int warps = (n_edges + 7) / 8;
        k_spmm2<<<(warps + 7) / 8, 256>>>(src, dst, out, n_edges);
    }
    k_final<<<(n_nodes * (OUT_DIM / 4) + 255) / 256, 256>>>(out, b2, n_nodes);
}

// round 9
// speedup vs baseline: 1.0468x; 1.0468x over previous
#include <cuda_runtime.h>
#include <cuda_bf16.h>
#include <cuda_fp16.h>
#include <stdint.h>

#define NN 100000
#define NN_PAD 100096
#define NE 1600000
#define IN_DIM 128
#define HID_DIM 256
#define OUT_DIM 64

// ---------------- device scratch ----------------
__device__ __align__(16) float g_norm_src[NN_PAD];
__device__ __align__(16) float g_norm_dst[NN_PAD];
__device__ __align__(16) __half g_h16[(size_t)NN * IN_DIM];          // fp16 copy of h
__device__ __align__(16) float g_xagg[(size_t)NN_PAD * IN_DIM];
__device__ __align__(16) __nv_bfloat16 g_xa_hi[(size_t)NN_PAD * IN_DIM];
__device__ __align__(16) __nv_bfloat16 g_xa_lo[(size_t)NN_PAD * IN_DIM];
__device__ __align__(16) __nv_bfloat16 g_w1t_hi[HID_DIM * IN_DIM];   // [n][k]
__device__ __align__(16) __nv_bfloat16 g_w1t_lo[HID_DIM * IN_DIM];
__device__ __align__(16) __nv_bfloat16 g_w2t_hi[OUT_DIM * HID_DIM];  // [n][k]
__device__ __align__(16) __nv_bfloat16 g_w2t_lo[OUT_DIM * HID_DIM];
__device__ __align__(16) __nv_bfloat16 g_hid_hi[(size_t)NN_PAD * HID_DIM];
__device__ __align__(16) __nv_bfloat16 g_hid_lo[(size_t)NN_PAD * HID_DIM];
__device__ __align__(16) float g_ypre[(size_t)NN * OUT_DIM];

__device__ __forceinline__ void split_bf16(float v, __nv_bfloat16& hi, __nv_bfloat16& lo) {
    hi = __float2bfloat16(v);
    lo = __float2bfloat16(v - __bfloat162float(hi));
}

#define MMA_BF16(d, a, b0, b1)                                                  \
    asm volatile("mma.sync.aligned.m16n8k16.row.col.f32.bf16.bf16.f32 "         \
                 "{%0,%1,%2,%3}, {%4,%5,%6,%7}, {%8,%9}, {%0,%1,%2,%3};"        \
                 : "+f"(d[0]), "+f"(d[1]), "+f"(d[2]), "+f"(d[3])               \
                 : "r"(a[0]), "r"(a[1]), "r"(a[2]), "r"(a[3]), "r"(b0), "r"(b1))

// ---------------- zero init + h->fp16 convert ----------------
__global__ void k_zero(const float* __restrict__ h, float4* __restrict__ dout4, int n_nodes) {
    int i = blockIdx.x * blockDim.x + threadIdx.x;
    int stride = gridDim.x * blockDim.x;
    const float4 z = make_float4(0.f, 0.f, 0.f, 0.f);
    const int nx4 = NN_PAD * (IN_DIM / 4);
    float4* xagg4 = reinterpret_cast<float4*>(g_xagg);
    for (int j = i; j < nx4; j += stride) xagg4[j] = z;
    const int no4 = n_nodes * (OUT_DIM / 4);
    for (int j = i; j < no4; j += stride) dout4[j] = z;
    for (int j = i; j < NN_PAD; j += stride) { g_norm_src[j] = 0.f; g_norm_dst[j] = 0.f; }
    const int hid_pad4 = (NN_PAD - NN) * (HID_DIM / 4);
    uint2* hh = reinterpret_cast<uint2*>(g_hid_hi + (size_t)NN * HID_DIM);
    uint2* hl = reinterpret_cast<uint2*>(g_hid_lo + (size_t)NN * HID_DIM);
    const uint2 z2 = make_uint2(0u, 0u);
    for (int j = i; j < hid_pad4; j += stride) { hh[j] = z2; hl[j] = z2; }
    // convert h (fp32) -> g_h16 (fp16)
    const int nh4 = NN * (IN_DIM / 4);
    for (int j = i; j < nh4; j += stride) {
        float4 v = reinterpret_cast<const float4*>(h)[j];
        __half2 a = __floats2half2_rn(v.x, v.y);
        __half2 b = __floats2half2_rn(v.z, v.w);
        uint2 pk;
        pk.x = *reinterpret_cast<uint32_t*>(&a);
        pk.y = *reinterpret_cast<uint32_t*>(&b);
        reinterpret_cast<uint2*>(g_h16)[j] = pk;
    }
}

// ---------------- degrees ----------------
__global__ void k_degree(const int* __restrict__ src, const int* __restrict__ dst, int n_edges) {
    int i = blockIdx.x * blockDim.x + threadIdx.x;
    int stride = gridDim.x * blockDim.x;
    for (int e = i; e < n_edges; e += stride) {
        atomicAdd(&g_norm_src[src[e]], 1.0f);
        atomicAdd(&g_norm_dst[dst[e]], 1.0f);
    }
}

__global__ void k_norm(int n_nodes) {
    int i = blockIdx.x * blockDim.x + threadIdx.x;
    if (i < n_nodes) {
        g_norm_src[i] = rsqrtf(fmaxf(g_norm_src[i], 1.0f));
        g_norm_dst[i] = rsqrtf(fmaxf(g_norm_dst[i], 1.0f));
    }
}

// ---------------- pre-split weights (transposed [n][k]) ----------------
__global__ void k_prepw(const float* __restrict__ W1, const float* __restrict__ W2) {
    int i = blockIdx.x * blockDim.x + threadIdx.x;
    const int n1 = HID_DIM * IN_DIM;
    const int n2 = OUT_DIM * HID_DIM;
    if (i < n1) {
        int n = i / IN_DIM, k = i % IN_DIM;
        float v = W1[(size_t)k * HID_DIM + n];
        __nv_bfloat16 hi, lo;
        split_bf16(v, hi, lo);
        g_w1t_hi[i] = hi; g_w1t_lo[i] = lo;
    } else if (i < n1 + n2) {
        int j = i - n1;
        int n = j / HID_DIM, k = j % HID_DIM;
        float v = W2[(size_t)k * OUT_DIM + n];
        __nv_bfloat16 hi, lo;
        split_bf16(v, hi, lo);
        g_w2t_hi[j] = hi; g_w2t_lo[j] = lo;
    }
}

// ---------------- SpMM1: xagg[dst] += h16[src]*norm_src[src], 4 edges/warp ----------------
// fp16 gather (8B/lane), fp32 RED (16B/lane)
__global__ void k_spmm1(const int* __restrict__ src, const int* __restrict__ dst,
                        int n_edges) {
    int w = (blockIdx.x * blockDim.x + threadIdx.x) >> 5;
    int lane = threadIdx.x & 31;
    int e0 = w * 4;
    if (e0 >= n_edges) return;
    int s[4], d[4];
    float ns[4];
    #pragma unroll
    for (int i = 0; i < 4; i++) {
        int e = min(e0 + i, n_edges - 1);
        s[i] = __ldg(&src[e]);
        d[i] = __ldg(&dst[e]);
    }
    #pragma unroll
    for (int i = 0; i < 4; i++) ns[i] = g_norm_src[s[i]];
    uint2 v[4];
    #pragma unroll
    for (int i = 0; i < 4; i++)
        v[i] = reinterpret_cast<const uint2*>(g_h16 + (size_t)s[i] * IN_DIM)[lane];
    #pragma unroll
    for (int i = 0; i < 4; i++) {
        if (e0 + i >= n_edges) break;
        __half2 a = *reinterpret_cast<__half2*>(&v[i].x);
        __half2 b = *reinterpret_cast<__half2*>(&v[i].y);
        float2 fa = __half22float2(a);
        float2 fb = __half22float2(b);
        float4 t;
        t.x = fa.x * ns[i]; t.y = fa.y * ns[i];
        t.z = fb.x * ns[i]; t.w = fb.y * ns[i];
        float4* orow = reinterpret_cast<float4*>(g_xagg + (size_t)d[i] * IN_DIM);
        asm volatile("red.global.add.v4.f32 [%0], {%1,%2,%3,%4};"
                     :: "l"(orow + lane), "f"(t.x), "f"(t.y), "f"(t.z), "f"(t.w)
                     : "memory");
    }
}

// ---------------- split pass: xa = split(xagg * norm_dst) ----------------
__global__ void k_split() {
    int i = blockIdx.x * blockDim.x + threadIdx.x;
    int stride = gridDim.x * blockDim.x;
    const int total = NN_PAD * (IN_DIM / 4);
    for (int j = i; j < total; j += stride) {
        int row = j >> 5;
        float nd = g_norm_dst[row];
        float4 v = reinterpret_cast<const float4*>(g_xagg)[j];
        v.x *= nd; v.y *= nd; v.z *= nd; v.w *= nd;
        __nv_bfloat16 h0, l0, h1, l1, h2, l2, h3, l3;
        split_bf16(v.x, h0, l0); split_bf16(v.y, h1, l1);
        split_bf16(v.z, h2, l2); split_bf16(v.w, h3, l3);
        uint2 ph, pl;
        __nv_bfloat162 t0(h0, h1), t1(h2, h3);
        ph.x = *reinterpret_cast<uint32_t*>(&t0);
        ph.y = *reinterpret_cast<uint32_t*>(&t1);
        __nv_bfloat162 u0(l0, l1), u1(l2, l3);
        pl.x = *reinterpret_cast<uint32_t*>(&u0);
        pl.y = *reinterpret_cast<uint32_t*>(&u1);
        reinterpret_cast<uint2*>(g_xa_hi)[j] = ph;
        reinterpret_cast<uint2*>(g_xa_lo)[j] = pl;
    }
}

// ---------------- GEMM tiles ----------------
#define BM 128
#define BN 64
#define BK 32
#define KPAD 40

// GEMM1: hidden = relu(xa @ W1 + b1) * clip(p,0,1); split-bf16 store (R7 config)
__global__ __launch_bounds__(256) void k_gemm1(const float* __restrict__ b1,
                                               const float* __restrict__ p,
                                               int n_nodes) {
    __shared__ __align__(16) __nv_bfloat16 As_hi[BM * KPAD];
    __shared__ __align__(16) __nv_bfloat16 As_lo[BM * KPAD];
    __shared__ __align__(16) __nv_bfloat16 Bs_hi[BN * KPAD];
    __shared__ __align__(16) __nv_bfloat16 Bs_lo[BN * KPAD];

    const int m0 = blockIdx.x * BM;
    const int n0 = blockIdx.y * BN;
    const int tid = threadIdx.x;
    const int lane = tid & 31;
    const int wid = tid >> 5;
    const int warp_m = wid >> 2;
    const int warp_n = wid & 3;

    float acc[4][2][4];
    #pragma unroll
    for (int i = 0; i < 4; i++)
        #pragma unroll
        for (int j = 0; j < 2; j++)
            #pragma unroll
            for (int q = 0; q < 4; q++) acc[i][j][q] = 0.f;

    for (int k0 = 0; k0 < IN_DIM; k0 += BK) {
        #pragma unroll
        for (int i = 0; i < 2; i++) {
            int idx = tid + 256 * i;
            int row = idx >> 2;
            int q = idx & 3;
            uint4 vh = *reinterpret_cast<const uint4*>(&g_xa_hi[(size_t)(m0 + row) * IN_DIM + k0 + 8 * q]);
            uint4 vl = *reinterpret_cast<const uint4*>(&g_xa_lo[(size_t)(m0 + row) * IN_DIM + k0 + 8 * q]);
            *reinterpret_cast<uint4*>(&As_hi[row * KPAD + 8 * q]) = vh;
            *reinterpret_cast<uint4*>(&As_lo[row * KPAD + 8 * q]) = vl;
        }
        {
            int n = tid >> 2;
            int q = tid & 3;
            uint4 vh = *reinterpret_cast<const uint4*>(&g_w1t_hi[(size_t)(n0 + n) * IN_DIM + k0 + 8 * q]);
            uint4 vl = *reinterpret_cast<const uint4*>(&g_w1t_lo[(size_t)(n0 + n) * IN_DIM + k0 + 8 * q]);
            *reinterpret_cast<uint4*>(&Bs_hi[n * KPAD + 8 * q]) = vh;
            *reinterpret_cast<uint4*>(&Bs_lo[n * KPAD + 8 * q]) = vl;
        }
        __syncthreads();

        #pragma unroll
        for (int ks = 0; ks < 2; ks++) {
            const int kc = ks * 16 + 2 * (lane & 3);
            uint32_t ah[4][4], al[4][4];
            #pragma unroll
            for (int i = 0; i < 4; i++) {
                int r = warp_m * 64 + i * 16 + (lane >> 2);
                ah[i][0] = *reinterpret_cast<uint32_t*>(&As_hi[r * KPAD + kc]);
                ah[i][1] = *reinterpret_cast<uint32_t*>(&As_hi[(r + 8) * KPAD + kc]);
                ah[i][2] = *reinterpret_cast<uint32_t*>(&As_hi[r * KPAD + kc + 8]);
                ah[i][3] = *reinterpret_cast<uint32_t*>(&As_hi[(r + 8) * KPAD + kc + 8]);
                al[i][0] = *reinterpret_cast<uint32_t*>(&As_lo[r * KPAD + kc]);
                al[i][1] = *reinterpret_cast<uint32_t*>(&As_lo[(r + 8) * KPAD + kc]);
                al[i][2] = *reinterpret_cast<uint32_t*>(&As_lo[r * KPAD + kc + 8]);
                al[i][3] = *reinterpret_cast<uint32_t*>(&As_lo[(r + 8) * KPAD + kc + 8]);
            }
            #pragma unroll
            for (int j = 0; j < 2; j++) {
                int c = warp_n * 16 + j * 8 + (lane >> 2);
                uint32_t bh0 = *reinterpret_cast<uint32_t*>(&Bs_hi[c * KPAD + kc]);
                uint32_t bh1 = *reinterpret_cast<uint32_t*>(&Bs_hi[c * KPAD + kc + 8]);
                uint32_t bl0 = *reinterpret_cast<uint32_t*>(&Bs_lo[c * KPAD + kc]);
                uint32_t bl1 = *reinterpret_cast<uint32_t*>(&Bs_lo[c * KPAD + kc + 8]);
                #pragma unroll
                for (int i = 0; i < 4; i++) {
                    MMA_BF16(acc[i][j], ah[i], bh0, bh1);
                    MMA_BF16(acc[i][j], ah[i], bl0, bl1);
                    MMA_BF16(acc[i][j], al[i], bh0, bh1);
                }
            }
        }
        __syncthreads();
    }

    #pragma unroll
    for (int i = 0; i < 4; i++) {
        int r = warp_m * 64 + i * 16 + (lane >> 2);
        #pragma unroll
        for (int j = 0; j < 2; j++) {
            int c0 = n0 + warp_n * 16 + j * 8 + 2 * (lane & 3);
            float bb0 = b1[c0], bb1 = b1[c0 + 1];
            float p0 = fminf(fmaxf(p[c0], 0.f), 1.f);
            float p1 = fminf(fmaxf(p[c0 + 1], 0.f), 1.f);
            #pragma unroll
            for (int hrow = 0; hrow < 2; hrow++) {
                int grow = m0 + r + 8 * hrow;
                if (grow >= n_nodes) continue;
                float v0 = fmaxf(acc[i][j][2 * hrow + 0] + bb0, 0.f) * p0;
                float v1 = fmaxf(acc[i][j][2 * hrow + 1] + bb1, 0.f) * p1;
                __nv_bfloat16 h0, l0, h1, l1;
                split_bf16(v0, h0, l0);
                split_bf16(v1, h1, l1);
                *reinterpret_cast<__nv_bfloat162*>(&g_hid_hi[(size_t)grow * HID_DIM + c0]) = __nv_bfloat162(h0, h1);
                *reinterpret_cast<__nv_bfloat162*>(&g_hid_lo[(size_t)grow * HID_DIM + c0]) = __nv_bfloat162(l0, l1);
            }
        }
    }
}

// GEMM2: ypre = (hidden @ W2) * norm_src[row] (R7 config)
__global__ __launch_bounds__(256) void k_gemm2(int n_nodes) {
    __shared__ __align__(16) __nv_bfloat16 As_hi[BM * KPAD];
    __shared__ __align__(16) __nv_bfloat16 As_lo[BM * KPAD];
    __shared__ __align__(16) __nv_bfloat16 Bs_hi[BN * KPAD];
    __shared__ __align__(16) __nv_bfloat16 Bs_lo[BN * KPAD];

    const int m0 = blockIdx.x * BM;
    const int tid = threadIdx.x;
    const int lane = tid & 31;
    const int wid = tid >> 5;
    const int warp_m = wid >> 2;
    const int warp_n = wid & 3;

    float acc[4][2][4];
    #pragma unroll
    for (int i = 0; i < 4; i++)
        #pragma unroll
        for (int j = 0; j < 2; j++)
            #pragma unroll
            for (int q = 0; q < 4; q++) acc[i][j][q] = 0.f;

    for (int k0 = 0; k0 < HID_DIM; k0 += BK) {
        #pragma unroll
        for (int i = 0; i < 2; i++) {
            int idx = tid + 256 * i;
            int row = idx >> 2;
            int q = idx & 3;
            uint4 vh = *reinterpret_cast<const uint4*>(&g_hid_hi[(size_t)(m0 + row) * HID_DIM + k0 + 8 * q]);
            uint4 vl = *reinterpret_cast<const uint4*>(&g_hid_lo[(size_t)(m0 + row) * HID_DIM + k0 + 8 * q]);
            *reinterpret_cast<uint4*>(&As_hi[row * KPAD + 8 * q]) = vh;
            *reinterpret_cast<uint4*>(&As_lo[row * KPAD + 8 * q]) = vl;
        }
        {
            int n = tid >> 2;
            int q = tid & 3;
            uint4 vh = *reinterpret_cast<const uint4*>(&g_w2t_hi[(size_t)n * HID_DIM + k0 + 8 * q]);
            uint4 vl = *reinterpret_cast<const uint4*>(&g_w2t_lo[(size_t)n * HID_DIM + k0 + 8 * q]);
            *reinterpret_cast<uint4*>(&Bs_hi[n * KPAD + 8 * q]) = vh;
            *reinterpret_cast<uint4*>(&Bs_lo[n * KPAD + 8 * q]) = vl;
        }
        __syncthreads();

        #pragma unroll
        for (int ks = 0; ks < 2; ks++) {
            const int kc = ks * 16 + 2 * (lane & 3);
            uint32_t ah[4][4], al[4][4];
            #pragma unroll
            for (int i = 0; i < 4; i++) {
                int r = warp_m * 64 + i * 16 + (lane >> 2);
                ah[i][0] = *reinterpret_cast<uint32_t*>(&As_hi[r * KPAD + kc]);
                ah[i][1] = *reinterpret_cast<uint32_t*>(&As_hi[(r + 8) * KPAD + kc]);
                ah[i][2] = *reinterpret_cast<uint32_t*>(&As_hi[r * KPAD + kc + 8]);
                ah[i][3] = *reinterpret_cast<uint32_t*>(&As_hi[(r + 8) * KPAD + kc + 8]);
                al[i][0] = *reinterpret_cast<uint32_t*>(&As_lo[r * KPAD + kc]);
                al[i][1] = *reinterpret_cast<uint32_t*>(&As_lo[(r + 8) * KPAD + kc]);
                al[i][2] = *reinterpret_cast<uint32_t*>(&As_lo[r * KPAD + kc + 8]);
                al[i][3] = *reinterpret_cast<uint32_t*>(&As_lo[(r + 8) * KPAD + kc + 8]);
            }
            #pragma unroll
            for (int j = 0; j < 2; j++) {
                int c = warp_n * 16 + j * 8 + (lane >> 2);
                uint32_t bh0 = *reinterpret_cast<uint32_t*>(&Bs_hi[c * KPAD + kc]);
                uint32_t bh1 = *reinterpret_cast<uint32_t*>(&Bs_hi[c * KPAD + kc + 8]);
                uint32_t bl0 = *reinterpret_cast<uint32_t*>(&Bs_lo[c * KPAD + kc]);
                uint32_t bl1 = *reinterpret_cast<uint32_t*>(&Bs_lo[c * KPAD + kc + 8]);
                #pragma unroll
                for (int i = 0; i < 4; i++) {
                    MMA_BF16(acc[i][j], ah[i], bh0, bh1);
                    MMA_BF16(acc[i][j], ah[i], bl0, bl1);
                    MMA_BF16(acc[i][j], al[i], bh0, bh1);
                }
            }
        }
        __syncthreads();
    }

    #pragma unroll
    for (int i = 0; i < 4; i++) {
        int r = warp_m * 64 + i * 16 + (lane >> 2);
        #pragma unroll
        for (int j = 0; j < 2; j++) {
            int c0 = warp_n * 16 + j * 8 + 2 * (lane & 3);
            #pragma unroll
            for (int hrow = 0; hrow < 2; hrow++) {
                int grow = m0 + r + 8 * hrow;
                if (grow >= n_nodes) continue;
                float ns = g_norm_src[grow];
                float2 v;
                v.x = acc[i][j][2 * hrow + 0] * ns;
                v.y = acc[i][j][2 * hrow + 1] * ns;
                *reinterpret_cast<float2*>(&g_ypre[(size_t)grow * OUT_DIM + c0]) = v;
            }
        }
    }
}

// ---------------- SpMM2: out[dst] += ypre[src], 8 edges/warp (R2) ----------------
__global__ void k_spmm2(const int* __restrict__ src, const int* __restrict__ dst,
                        float* __restrict__ out, int n_edges) {
    int w = (blockIdx.x * blockDim.x + threadIdx.x) >> 5;
    int lane = threadIdx.x & 31;
    int half = lane >> 4;
    int l = lane & 15;
    int e0 = w * 8;
    if (e0 >= n_edges) return;
    int s[4], d[4];
    #pragma unroll
    for (int i = 0; i < 4; i++) {
        int e = min(e0 + 2 * i + half, n_edges - 1);
        s[i] = __ldg(&src[e]);
        d[i] = __ldg(&dst[e]);
    }
    float4 v[4];
    #pragma unroll
    for (int i = 0; i < 4; i++)
        v[i] = reinterpret_cast<const float4*>(g_ypre + (size_t)s[i] * OUT_DIM)[l];
    #pragma unroll
    for (int i = 0; i < 4; i++) {
        if (e0 + 2 * i + half >= n_edges) break;
        float4* orow = reinterpret_cast<float4*>(out + (size_t)d[i] * OUT_DIM);
        asm volatile("red.global.add.v4.f32 [%0], {%1,%2,%3,%4};"
                     :: "l"(orow + l), "f"(v[i].x), "f"(v[i].y), "f"(v[i].z), "f"(v[i].w)
                     : "memory");
    }
}

// ---------------- final: out = out * norm_dst[row] + b2[col] ----------------
__global__ void k_final(float* __restrict__ out, const float* __restrict__ b2, int n_nodes) {
    int i = blockIdx.x * blockDim.x + threadIdx.x;
    int total = n_nodes * (OUT_DIM / 4);
    if (i >= total) return;
    int row = i >> 4;
    int c4 = i & 15;
    float nd = g_norm_dst[row];
    float4 v = reinterpret_cast<float4*>(out)[i];
    const float4 bb = reinterpret_cast<const float4*>(b2)[c4];
    v.x = v.x * nd + bb.x;
    v.y = v.y * nd + bb.y;
    v.z = v.z * nd + bb.z;
    v.w = v.w * nd + bb.w;
    reinterpret_cast<float4*>(out)[i] = v;
}

// ---------------- launch ----------------
extern "C" void kernel_launch(void* const* d_in, const int* in_sizes, int n_in,
                              void* d_out, int out_size) {
    const float* h  = (const float*)d_in[0];
    const float* W1 = (const float*)d_in[1];
    const float* b1 = (const float*)d_in[2];
    const float* W2 = (const float*)d_in[3];
    const float* b2 = (const float*)d_in[4];
    const float* p  = (const float*)d_in[5];
    const int* src  = (const int*)d_in[6];
    const int* dst  = (const int*)d_in[7];

    const int n_nodes = in_sizes[0] / IN_DIM;   // 100000
    const int n_edges = in_sizes[6];            // 1600000
    float* out = (float*)d_out;

    k_zero<<<4096, 256>>>(h, reinterpret_cast<float4*>(out), n_nodes);
    k_prepw<<<(HID_DIM * IN_DIM + OUT_DIM * HID_DIM + 255) / 256, 256>>>(W1, W2);
    k_degree<<<(n_edges + 255) / 256, 256>>>(src, dst, n_edges);
    k_norm<<<(n_nodes + 255) / 256, 256>>>(n_nodes);

    // SpMM1: 4 edges per warp, fp16 gather
    {
        int warps = (n_edges + 3) / 4;
        k_spmm1<<<(warps + 7) / 8, 256>>>(src, dst, n_edges);
    }
    // split pass: xagg * norm_dst -> bf16 hi/lo
    k_split<<<2048, 256>>>();
    // GEMM1 (R7 config)
    {
        dim3 grid(NN_PAD / BM, HID_DIM / BN);   // 782 x 4
        k_gemm1<<<grid, 256>>>(b1, p, n_nodes);
    }
    // GEMM2 (R7 config)
    {
        dim3 grid(NN_PAD / BM, 1);              // 782
        k_gemm2<<<grid, 256>>>(n_nodes);
    }
    // SpMM2: 8 edges per warp
    {
        int warps = (n_edges + 7) / 8;
        k_spmm2<<<(warps + 7) / 8, 256>>>(src, dst, out, n_edges);
    }
    k_final<<<(n_nodes * (OUT_DIM / 4) + 255) / 256, 256>>>(out, b2, n_nodes);
}

// round 10
// speedup vs baseline: 1.0625x; 1.0150x over previous
#include <cuda_runtime.h>
#include <cuda_bf16.h>
#include <cuda_fp16.h>
#include <stdint.h>

#define NN 100000
#define NN_PAD 100096
#define NE 1600000
#define IN_DIM 128
#define HID_DIM 256
#define OUT_DIM 64

// ---------------- device scratch ----------------
__device__ __align__(16) float g_norm_src[NN_PAD];
__device__ __align__(16) float g_norm_dst[NN_PAD];
__device__ __align__(16) __half g_h16[(size_t)NN * IN_DIM];          // fp16 copy of h
__device__ __align__(16) float g_xagg[(size_t)NN_PAD * IN_DIM];
__device__ __align__(16) __nv_bfloat16 g_xa_hi[(size_t)NN_PAD * IN_DIM];
__device__ __align__(16) __nv_bfloat16 g_xa_lo[(size_t)NN_PAD * IN_DIM];
__device__ __align__(16) __nv_bfloat16 g_w1t_hi[HID_DIM * IN_DIM];   // [n][k]
__device__ __align__(16) __nv_bfloat16 g_w1t_lo[HID_DIM * IN_DIM];
__device__ __align__(16) __nv_bfloat16 g_w2t_hi[OUT_DIM * HID_DIM];  // [n][k]
__device__ __align__(16) __nv_bfloat16 g_w2t_lo[OUT_DIM * HID_DIM];
__device__ __align__(16) __nv_bfloat16 g_hid_hi[(size_t)NN_PAD * HID_DIM];
__device__ __align__(16) __nv_bfloat16 g_hid_lo[(size_t)NN_PAD * HID_DIM];
__device__ __align__(16) __half g_ypre16[(size_t)NN * OUT_DIM];      // fp16 ypre

__device__ __forceinline__ void split_bf16(float v, __nv_bfloat16& hi, __nv_bfloat16& lo) {
    hi = __float2bfloat16(v);
    lo = __float2bfloat16(v - __bfloat162float(hi));
}

#define MMA_BF16(d, a, b0, b1)                                                  \
    asm volatile("mma.sync.aligned.m16n8k16.row.col.f32.bf16.bf16.f32 "         \
                 "{%0,%1,%2,%3}, {%4,%5,%6,%7}, {%8,%9}, {%0,%1,%2,%3};"        \
                 : "+f"(d[0]), "+f"(d[1]), "+f"(d[2]), "+f"(d[3])               \
                 : "r"(a[0]), "r"(a[1]), "r"(a[2]), "r"(a[3]), "r"(b0), "r"(b1))

// ---------------- zero init + h->fp16 convert + out=b2 ----------------
__global__ void k_zero(const float* __restrict__ h, const float* __restrict__ b2,
                       float4* __restrict__ dout4, int n_nodes) {
    int i = blockIdx.x * blockDim.x + threadIdx.x;
    int stride = gridDim.x * blockDim.x;
    const float4 z = make_float4(0.f, 0.f, 0.f, 0.f);
    const int nx4 = NN_PAD * (IN_DIM / 4);
    float4* xagg4 = reinterpret_cast<float4*>(g_xagg);
    for (int j = i; j < nx4; j += stride) xagg4[j] = z;
    // out rows = b2 (RED target; bias pre-applied, final fused into spmm2)
    const float4* b24 = reinterpret_cast<const float4*>(b2);
    const int no4 = n_nodes * (OUT_DIM / 4);
    for (int j = i; j < no4; j += stride) dout4[j] = b24[j & 15];
    for (int j = i; j < NN_PAD; j += stride) { g_norm_src[j] = 0.f; g_norm_dst[j] = 0.f; }
    const int hid_pad4 = (NN_PAD - NN) * (HID_DIM / 4);
    uint2* hh = reinterpret_cast<uint2*>(g_hid_hi + (size_t)NN * HID_DIM);
    uint2* hl = reinterpret_cast<uint2*>(g_hid_lo + (size_t)NN * HID_DIM);
    const uint2 z2 = make_uint2(0u, 0u);
    for (int j = i; j < hid_pad4; j += stride) { hh[j] = z2; hl[j] = z2; }
    // convert h (fp32) -> g_h16 (fp16)
    const int nh4 = NN * (IN_DIM / 4);
    for (int j = i; j < nh4; j += stride) {
        float4 v = reinterpret_cast<const float4*>(h)[j];
        __half2 a = __floats2half2_rn(v.x, v.y);
        __half2 b = __floats2half2_rn(v.z, v.w);
        uint2 pk;
        pk.x = *reinterpret_cast<uint32_t*>(&a);
        pk.y = *reinterpret_cast<uint32_t*>(&b);
        reinterpret_cast<uint2*>(g_h16)[j] = pk;
    }
}

// ---------------- degrees ----------------
__global__ void k_degree(const int* __restrict__ src, const int* __restrict__ dst, int n_edges) {
    int i = blockIdx.x * blockDim.x + threadIdx.x;
    int stride = gridDim.x * blockDim.x;
    for (int e = i; e < n_edges; e += stride) {
        atomicAdd(&g_norm_src[src[e]], 1.0f);
        atomicAdd(&g_norm_dst[dst[e]], 1.0f);
    }
}

__global__ void k_norm(int n_nodes) {
    int i = blockIdx.x * blockDim.x + threadIdx.x;
    if (i < n_nodes) {
        g_norm_src[i] = rsqrtf(fmaxf(g_norm_src[i], 1.0f));
        g_norm_dst[i] = rsqrtf(fmaxf(g_norm_dst[i], 1.0f));
    }
}

// ---------------- pre-split weights (transposed [n][k]) ----------------
__global__ void k_prepw(const float* __restrict__ W1, const float* __restrict__ W2) {
    int i = blockIdx.x * blockDim.x + threadIdx.x;
    const int n1 = HID_DIM * IN_DIM;
    const int n2 = OUT_DIM * HID_DIM;
    if (i < n1) {
        int n = i / IN_DIM, k = i % IN_DIM;
        float v = W1[(size_t)k * HID_DIM + n];
        __nv_bfloat16 hi, lo;
        split_bf16(v, hi, lo);
        g_w1t_hi[i] = hi; g_w1t_lo[i] = lo;
    } else if (i < n1 + n2) {
        int j = i - n1;
        int n = j / HID_DIM, k = j % HID_DIM;
        float v = W2[(size_t)k * OUT_DIM + n];
        __nv_bfloat16 hi, lo;
        split_bf16(v, hi, lo);
        g_w2t_hi[j] = hi; g_w2t_lo[j] = lo;
    }
}

// ---------------- SpMM1: xagg[dst] += h16[src]*norm_src[src], 4 edges/warp ----------------
__global__ void k_spmm1(const int* __restrict__ src, const int* __restrict__ dst,
                        int n_edges) {
    int w = (blockIdx.x * blockDim.x + threadIdx.x) >> 5;
    int lane = threadIdx.x & 31;
    int e0 = w * 4;
    if (e0 >= n_edges) return;
    int s[4], d[4];
    float ns[4];
    #pragma unroll
    for (int i = 0; i < 4; i++) {
        int e = min(e0 + i, n_edges - 1);
        s[i] = __ldg(&src[e]);
        d[i] = __ldg(&dst[e]);
    }
    #pragma unroll
    for (int i = 0; i < 4; i++) ns[i] = g_norm_src[s[i]];
    uint2 v[4];
    #pragma unroll
    for (int i = 0; i < 4; i++)
        v[i] = reinterpret_cast<const uint2*>(g_h16 + (size_t)s[i] * IN_DIM)[lane];
    #pragma unroll
    for (int i = 0; i < 4; i++) {
        if (e0 + i >= n_edges) break;
        __half2 a = *reinterpret_cast<__half2*>(&v[i].x);
        __half2 b = *reinterpret_cast<__half2*>(&v[i].y);
        float2 fa = __half22float2(a);
        float2 fb = __half22float2(b);
        float4 t;
        t.x = fa.x * ns[i]; t.y = fa.y * ns[i];
        t.z = fb.x * ns[i]; t.w = fb.y * ns[i];
        float4* orow = reinterpret_cast<float4*>(g_xagg + (size_t)d[i] * IN_DIM);
        asm volatile("red.global.add.v4.f32 [%0], {%1,%2,%3,%4};"
                     :: "l"(orow + lane), "f"(t.x), "f"(t.y), "f"(t.z), "f"(t.w)
                     : "memory");
    }
}

// ---------------- split pass: xa = split(xagg * norm_dst) ----------------
__global__ void k_split() {
    int i = blockIdx.x * blockDim.x + threadIdx.x;
    int stride = gridDim.x * blockDim.x;
    const int total = NN_PAD * (IN_DIM / 4);
    for (int j = i; j < total; j += stride) {
        int row = j >> 5;
        float nd = g_norm_dst[row];
        float4 v = reinterpret_cast<const float4*>(g_xagg)[j];
        v.x *= nd; v.y *= nd; v.z *= nd; v.w *= nd;
        __nv_bfloat16 h0, l0, h1, l1, h2, l2, h3, l3;
        split_bf16(v.x, h0, l0); split_bf16(v.y, h1, l1);
        split_bf16(v.z, h2, l2); split_bf16(v.w, h3, l3);
        uint2 ph, pl;
        __nv_bfloat162 t0(h0, h1), t1(h2, h3);
        ph.x = *reinterpret_cast<uint32_t*>(&t0);
        ph.y = *reinterpret_cast<uint32_t*>(&t1);
        __nv_bfloat162 u0(l0, l1), u1(l2, l3);
        pl.x = *reinterpret_cast<uint32_t*>(&u0);
        pl.y = *reinterpret_cast<uint32_t*>(&u1);
        reinterpret_cast<uint2*>(g_xa_hi)[j] = ph;
        reinterpret_cast<uint2*>(g_xa_lo)[j] = pl;
    }
}

// ---------------- GEMM tiles ----------------
#define BM 128
#define BN 64
#define BK 32
#define KPAD 40

// GEMM1: hidden = relu(xa @ W1 + b1) * clip(p,0,1); split-bf16 store (R7 config)
__global__ __launch_bounds__(256) void k_gemm1(const float* __restrict__ b1,
                                               const float* __restrict__ p,
                                               int n_nodes) {
    __shared__ __align__(16) __nv_bfloat16 As_hi[BM * KPAD];
    __shared__ __align__(16) __nv_bfloat16 As_lo[BM * KPAD];
    __shared__ __align__(16) __nv_bfloat16 Bs_hi[BN * KPAD];
    __shared__ __align__(16) __nv_bfloat16 Bs_lo[BN * KPAD];

    const int m0 = blockIdx.x * BM;
    const int n0 = blockIdx.y * BN;
    const int tid = threadIdx.x;
    const int lane = tid & 31;
    const int wid = tid >> 5;
    const int warp_m = wid >> 2;
    const int warp_n = wid & 3;

    float acc[4][2][4];
    #pragma unroll
    for (int i = 0; i < 4; i++)
        #pragma unroll
        for (int j = 0; j < 2; j++)
            #pragma unroll
            for (int q = 0; q < 4; q++) acc[i][j][q] = 0.f;

    for (int k0 = 0; k0 < IN_DIM; k0 += BK) {
        #pragma unroll
        for (int i = 0; i < 2; i++) {
            int idx = tid + 256 * i;
            int row = idx >> 2;
            int q = idx & 3;
            uint4 vh = *reinterpret_cast<const uint4*>(&g_xa_hi[(size_t)(m0 + row) * IN_DIM + k0 + 8 * q]);
            uint4 vl = *reinterpret_cast<const uint4*>(&g_xa_lo[(size_t)(m0 + row) * IN_DIM + k0 + 8 * q]);
            *reinterpret_cast<uint4*>(&As_hi[row * KPAD + 8 * q]) = vh;
            *reinterpret_cast<uint4*>(&As_lo[row * KPAD + 8 * q]) = vl;
        }
        {
            int n = tid >> 2;
            int q = tid & 3;
            uint4 vh = *reinterpret_cast<const uint4*>(&g_w1t_hi[(size_t)(n0 + n) * IN_DIM + k0 + 8 * q]);
            uint4 vl = *reinterpret_cast<const uint4*>(&g_w1t_lo[(size_t)(n0 + n) * IN_DIM + k0 + 8 * q]);
            *reinterpret_cast<uint4*>(&Bs_hi[n * KPAD + 8 * q]) = vh;
            *reinterpret_cast<uint4*>(&Bs_lo[n * KPAD + 8 * q]) = vl;
        }
        __syncthreads();

        #pragma unroll
        for (int ks = 0; ks < 2; ks++) {
            const int kc = ks * 16 + 2 * (lane & 3);
            uint32_t ah[4][4], al[4][4];
            #pragma unroll
            for (int i = 0; i < 4; i++) {
                int r = warp_m * 64 + i * 16 + (lane >> 2);
                ah[i][0] = *reinterpret_cast<uint32_t*>(&As_hi[r * KPAD + kc]);
                ah[i][1] = *reinterpret_cast<uint32_t*>(&As_hi[(r + 8) * KPAD + kc]);
                ah[i][2] = *reinterpret_cast<uint32_t*>(&As_hi[r * KPAD + kc + 8]);
                ah[i][3] = *reinterpret_cast<uint32_t*>(&As_hi[(r + 8) * KPAD + kc + 8]);
                al[i][0] = *reinterpret_cast<uint32_t*>(&As_lo[r * KPAD + kc]);
                al[i][1] = *reinterpret_cast<uint32_t*>(&As_lo[(r + 8) * KPAD + kc]);
                al[i][2] = *reinterpret_cast<uint32_t*>(&As_lo[r * KPAD + kc + 8]);
                al[i][3] = *reinterpret_cast<uint32_t*>(&As_lo[(r + 8) * KPAD + kc + 8]);
            }
            #pragma unroll
            for (int j = 0; j < 2; j++) {
                int c = warp_n * 16 + j * 8 + (lane >> 2);
                uint32_t bh0 = *reinterpret_cast<uint32_t*>(&Bs_hi[c * KPAD + kc]);
                uint32_t bh1 = *reinterpret_cast<uint32_t*>(&Bs_hi[c * KPAD + kc + 8]);
                uint32_t bl0 = *reinterpret_cast<uint32_t*>(&Bs_lo[c * KPAD + kc]);
                uint32_t bl1 = *reinterpret_cast<uint32_t*>(&Bs_lo[c * KPAD + kc + 8]);
                #pragma unroll
                for (int i = 0; i < 4; i++) {
                    MMA_BF16(acc[i][j], ah[i], bh0, bh1);
                    MMA_BF16(acc[i][j], ah[i], bl0, bl1);
                    MMA_BF16(acc[i][j], al[i], bh0, bh1);
                }
            }
        }
        __syncthreads();
    }

    #pragma unroll
    for (int i = 0; i < 4; i++) {
        int r = warp_m * 64 + i * 16 + (lane >> 2);
        #pragma unroll
        for (int j = 0; j < 2; j++) {
            int c0 = n0 + warp_n * 16 + j * 8 + 2 * (lane & 3);
            float bb0 = b1[c0], bb1 = b1[c0 + 1];
            float p0 = fminf(fmaxf(p[c0], 0.f), 1.f);
            float p1 = fminf(fmaxf(p[c0 + 1], 0.f), 1.f);
            #pragma unroll
            for (int hrow = 0; hrow < 2; hrow++) {
                int grow = m0 + r + 8 * hrow;
                if (grow >= n_nodes) continue;
                float v0 = fmaxf(acc[i][j][2 * hrow + 0] + bb0, 0.f) * p0;
                float v1 = fmaxf(acc[i][j][2 * hrow + 1] + bb1, 0.f) * p1;
                __nv_bfloat16 h0, l0, h1, l1;
                split_bf16(v0, h0, l0);
                split_bf16(v1, h1, l1);
                *reinterpret_cast<__nv_bfloat162*>(&g_hid_hi[(size_t)grow * HID_DIM + c0]) = __nv_bfloat162(h0, h1);
                *reinterpret_cast<__nv_bfloat162*>(&g_hid_lo[(size_t)grow * HID_DIM + c0]) = __nv_bfloat162(l0, l1);
            }
        }
    }
}

// GEMM2: ypre16 = fp16((hidden @ W2) * norm_src[row]) (R7 config, fp16 store)
__global__ __launch_bounds__(256) void k_gemm2(int n_nodes) {
    __shared__ __align__(16) __nv_bfloat16 As_hi[BM * KPAD];
    __shared__ __align__(16) __nv_bfloat16 As_lo[BM * KPAD];
    __shared__ __align__(16) __nv_bfloat16 Bs_hi[BN * KPAD];
    __shared__ __align__(16) __nv_bfloat16 Bs_lo[BN * KPAD];

    const int m0 = blockIdx.x * BM;
    const int tid = threadIdx.x;
    const int lane = tid & 31;
    const int wid = tid >> 5;
    const int warp_m = wid >> 2;
    const int warp_n = wid & 3;

    float acc[4][2][4];
    #pragma unroll
    for (int i = 0; i < 4; i++)
        #pragma unroll
        for (int j = 0; j < 2; j++)
            #pragma unroll
            for (int q = 0; q < 4; q++) acc[i][j][q] = 0.f;

    for (int k0 = 0; k0 < HID_DIM; k0 += BK) {
        #pragma unroll
        for (int i = 0; i < 2; i++) {
            int idx = tid + 256 * i;
            int row = idx >> 2;
            int q = idx & 3;
            uint4 vh = *reinterpret_cast<const uint4*>(&g_hid_hi[(size_t)(m0 + row) * HID_DIM + k0 + 8 * q]);
            uint4 vl = *reinterpret_cast<const uint4*>(&g_hid_lo[(size_t)(m0 + row) * HID_DIM + k0 + 8 * q]);
            *reinterpret_cast<uint4*>(&As_hi[row * KPAD + 8 * q]) = vh;
            *reinterpret_cast<uint4*>(&As_lo[row * KPAD + 8 * q]) = vl;
        }
        {
            int n = tid >> 2;
            int q = tid & 3;
            uint4 vh = *reinterpret_cast<const uint4*>(&g_w2t_hi[(size_t)n * HID_DIM + k0 + 8 * q]);
            uint4 vl = *reinterpret_cast<const uint4*>(&g_w2t_lo[(size_t)n * HID_DIM + k0 + 8 * q]);
            *reinterpret_cast<uint4*>(&Bs_hi[n * KPAD + 8 * q]) = vh;
            *reinterpret_cast<uint4*>(&Bs_lo[n * KPAD + 8 * q]) = vl;
        }
        __syncthreads();

        #pragma unroll
        for (int ks = 0; ks < 2; ks++) {
            const int kc = ks * 16 + 2 * (lane & 3);
            uint32_t ah[4][4], al[4][4];
            #pragma unroll
            for (int i = 0; i < 4; i++) {
                int r = warp_m * 64 + i * 16 + (lane >> 2);
                ah[i][0] = *reinterpret_cast<uint32_t*>(&As_hi[r * KPAD + kc]);
                ah[i][1] = *reinterpret_cast<uint32_t*>(&As_hi[(r + 8) * KPAD + kc]);
                ah[i][2] = *reinterpret_cast<uint32_t*>(&As_hi[r * KPAD + kc + 8]);
                ah[i][3] = *reinterpret_cast<uint32_t*>(&As_hi[(r + 8) * KPAD + kc + 8]);
                al[i][0] = *reinterpret_cast<uint32_t*>(&As_lo[r * KPAD + kc]);
                al[i][1] = *reinterpret_cast<uint32_t*>(&As_lo[(r + 8) * KPAD + kc]);
                al[i][2] = *reinterpret_cast<uint32_t*>(&As_lo[r * KPAD + kc + 8]);
                al[i][3] = *reinterpret_cast<uint32_t*>(&As_lo[(r + 8) * KPAD + kc + 8]);
            }
            #pragma unroll
            for (int j = 0; j < 2; j++) {
                int c = warp_n * 16 + j * 8 + (lane >> 2);
                uint32_t bh0 = *reinterpret_cast<uint32_t*>(&Bs_hi[c * KPAD + kc]);
                uint32_t bh1 = *reinterpret_cast<uint32_t*>(&Bs_hi[c * KPAD + kc + 8]);
                uint32_t bl0 = *reinterpret_cast<uint32_t*>(&Bs_lo[c * KPAD + kc]);
                uint32_t bl1 = *reinterpret_cast<uint32_t*>(&Bs_lo[c * KPAD + kc + 8]);
                #pragma unroll
                for (int i = 0; i < 4; i++) {
                    MMA_BF16(acc[i][j], ah[i], bh0, bh1);
                    MMA_BF16(acc[i][j], ah[i], bl0, bl1);
                    MMA_BF16(acc[i][j], al[i], bh0, bh1);
                }
            }
        }
        __syncthreads();
    }

    #pragma unroll
    for (int i = 0; i < 4; i++) {
        int r = warp_m * 64 + i * 16 + (lane >> 2);
        #pragma unroll
        for (int j = 0; j < 2; j++) {
            int c0 = warp_n * 16 + j * 8 + 2 * (lane & 3);
            #pragma unroll
            for (int hrow = 0; hrow < 2; hrow++) {
                int grow = m0 + r + 8 * hrow;
                if (grow >= n_nodes) continue;
                float ns = g_norm_src[grow];
                __half2 v = __floats2half2_rn(acc[i][j][2 * hrow + 0] * ns,
                                              acc[i][j][2 * hrow + 1] * ns);
                *reinterpret_cast<__half2*>(&g_ypre16[(size_t)grow * OUT_DIM + c0]) = v;
            }
        }
    }
}

// ---------------- SpMM2 (fused final): out[dst] += ypre16[src]*norm_dst[dst]; out pre-init b2 ----------------
// half-warp per edge, 8 edges/warp; fp16 gather (8B/lane), fp32 RED (16B/lane)
__global__ void k_spmm2(const int* __restrict__ src, const int* __restrict__ dst,
                        float* __restrict__ out, int n_edges) {
    int w = (blockIdx.x * blockDim.x + threadIdx.x) >> 5;
    int lane = threadIdx.x & 31;
    int half = lane >> 4;
    int l = lane & 15;
    int e0 = w * 8;
    if (e0 >= n_edges) return;
    int s[4], d[4];
    #pragma unroll
    for (int i = 0; i < 4; i++) {
        int e = min(e0 + 2 * i + half, n_edges - 1);
        s[i] = __ldg(&src[e]);
        d[i] = __ldg(&dst[e]);
    }
    float nd[4];
    #pragma unroll
    for (int i = 0; i < 4; i++) nd[i] = g_norm_dst[d[i]];
    uint2 v[4];
    #pragma unroll
    for (int i = 0; i < 4; i++)
        v[i] = reinterpret_cast<const uint2*>(g_ypre16 + (size_t)s[i] * OUT_DIM)[l];
    #pragma unroll
    for (int i = 0; i < 4; i++) {
        if (e0 + 2 * i + half >= n_edges) break;
        __half2 a = *reinterpret_cast<__half2*>(&v[i].x);
        __half2 b = *reinterpret_cast<__half2*>(&v[i].y);
        float2 fa = __half22float2(a);
        float2 fb = __half22float2(b);
        float4 t;
        t.x = fa.x * nd[i]; t.y = fa.y * nd[i];
        t.z = fb.x * nd[i]; t.w = fb.y * nd[i];
        float4* orow = reinterpret_cast<float4*>(out + (size_t)d[i] * OUT_DIM);
        asm volatile("red.global.add.v4.f32 [%0], {%1,%2,%3,%4};"
                     :: "l"(orow + l), "f"(t.x), "f"(t.y), "f"(t.z), "f"(t.w)
                     : "memory");
    }
}

// ---------------- launch ----------------
extern "C" void kernel_launch(void* const* d_in, const int* in_sizes, int n_in,
                              void* d_out, int out_size) {
    const float* h  = (const float*)d_in[0];
    const float* W1 = (const float*)d_in[1];
    const float* b1 = (const float*)d_in[2];
    const float* W2 = (const float*)d_in[3];
    const float* b2 = (const float*)d_in[4];
    const float* p  = (const float*)d_in[5];
    const int* src  = (const int*)d_in[6];
    const int* dst  = (const int*)d_in[7];

    const int n_nodes = in_sizes[0] / IN_DIM;   // 100000
    const int n_edges = in_sizes[6];            // 1600000
    float* out = (float*)d_out;

    k_zero<<<4096, 256>>>(h, b2, reinterpret_cast<float4*>(out), n_nodes);
    k_prepw<<<(HID_DIM * IN_DIM + OUT_DIM * HID_DIM + 255) / 256, 256>>>(W1, W2);
    k_degree<<<(n_edges + 255) / 256, 256>>>(src, dst, n_edges);
    k_norm<<<(n_nodes + 255) / 256, 256>>>(n_nodes);

    // SpMM1: 4 edges per warp, fp16 gather
    {
        int warps = (n_edges + 3) / 4;
        k_spmm1<<<(warps + 7) / 8, 256>>>(src, dst, n_edges);
    }
    // split pass: xagg * norm_dst -> bf16 hi/lo
    k_split<<<2048, 256>>>();
    // GEMM1 (R7 config)
    {
        dim3 grid(NN_PAD / BM, HID_DIM / BN);   // 782 x 4
        k_gemm1<<<grid, 256>>>(b1, p, n_nodes);
    }
    // GEMM2 (R7 config, fp16 epilogue)
    {
        dim3 grid(NN_PAD / BM, 1);              // 782
        k_gemm2<<<grid, 256>>>(n_nodes);
    }
    // SpMM2: 8 edges per warp, fp16 gather, fused norm_dst + bias
    {
        int warps = (n_edges + 7) / 8;
        k_spmm2<<<(warps + 7) / 8, 256>>>(src, dst, out, n_edges);
    }
}

// round 11
// speedup vs baseline: 1.1190x; 1.0532x over previous
#include <cuda_runtime.h>
#include <cuda_bf16.h>
#include <cuda_fp16.h>
#include <stdint.h>

#define NN 100000
#define NN_PAD 100096
#define NE 1600000
#define IN_DIM 128
#define HID_DIM 256
#define OUT_DIM 64

// ---------------- device scratch ----------------
__device__ __align__(16) float g_norm_src[NN_PAD];
__device__ __align__(16) float g_norm_dst[NN_PAD];
__device__ __align__(16) __half g_h16[(size_t)NN * IN_DIM];
__device__ __align__(16) float g_xagg[(size_t)NN_PAD * IN_DIM];
__device__ __align__(16) __nv_bfloat16 g_xa_hi[(size_t)NN_PAD * IN_DIM];
__device__ __align__(16) __nv_bfloat16 g_xa_lo[(size_t)NN_PAD * IN_DIM];
__device__ __align__(16) __nv_bfloat16 g_w1t_hi[HID_DIM * IN_DIM];   // [n][k]
__device__ __align__(16) __nv_bfloat16 g_w1t_lo[HID_DIM * IN_DIM];
__device__ __align__(16) __nv_bfloat16 g_w2t_hi[OUT_DIM * HID_DIM];  // [n][k]
__device__ __align__(16) __nv_bfloat16 g_w2t_lo[OUT_DIM * HID_DIM];
__device__ __align__(16) __nv_bfloat16 g_hid_hi[(size_t)NN_PAD * HID_DIM];
__device__ __align__(16) __nv_bfloat16 g_hid_lo[(size_t)NN_PAD * HID_DIM];
__device__ __align__(16) __half g_ypre16[(size_t)NN * OUT_DIM];

__device__ __forceinline__ void split_bf16(float v, __nv_bfloat16& hi, __nv_bfloat16& lo) {
    hi = __float2bfloat16(v);
    lo = __float2bfloat16(v - __bfloat162float(hi));
}

#define MMA_BF16(d, a, b0, b1)                                                  \
    asm volatile("mma.sync.aligned.m16n8k16.row.col.f32.bf16.bf16.f32 "         \
                 "{%0,%1,%2,%3}, {%4,%5,%6,%7}, {%8,%9}, {%0,%1,%2,%3};"        \
                 : "+f"(d[0]), "+f"(d[1]), "+f"(d[2]), "+f"(d[3])               \
                 : "r"(a[0]), "r"(a[1]), "r"(a[2]), "r"(a[3]), "r"(b0), "r"(b1))

__device__ __forceinline__ void cp16(void* smem_dst, const void* gmem_src) {
    uint32_t s = (uint32_t)__cvta_generic_to_shared(smem_dst);
    asm volatile("cp.async.cg.shared.global [%0], [%1], 16;" :: "r"(s), "l"(gmem_src) : "memory");
}
#define CP_COMMIT() asm volatile("cp.async.commit_group;" ::: "memory")
#define CP_WAIT(n)  asm volatile("cp.async.wait_group %0;" :: "n"(n) : "memory")

// ---------------- zero init + h->fp16 convert + out=b2 ----------------
__global__ void k_zero(const float* __restrict__ h, const float* __restrict__ b2,
                       float4* __restrict__ dout4, int n_nodes) {
    int i = blockIdx.x * blockDim.x + threadIdx.x;
    int stride = gridDim.x * blockDim.x;
    const float4 z = make_float4(0.f, 0.f, 0.f, 0.f);
    const int nx4 = NN_PAD * (IN_DIM / 4);
    float4* xagg4 = reinterpret_cast<float4*>(g_xagg);
    for (int j = i; j < nx4; j += stride) xagg4[j] = z;
    const float4* b24 = reinterpret_cast<const float4*>(b2);
    const int no4 = n_nodes * (OUT_DIM / 4);
    for (int j = i; j < no4; j += stride) dout4[j] = b24[j & 15];
    for (int j = i; j < NN_PAD; j += stride) { g_norm_src[j] = 0.f; g_norm_dst[j] = 0.f; }
    const int hid_pad4 = (NN_PAD - NN) * (HID_DIM / 4);
    uint2* hh = reinterpret_cast<uint2*>(g_hid_hi + (size_t)NN * HID_DIM);
    uint2* hl = reinterpret_cast<uint2*>(g_hid_lo + (size_t)NN * HID_DIM);
    const uint2 z2 = make_uint2(0u, 0u);
    for (int j = i; j < hid_pad4; j += stride) { hh[j] = z2; hl[j] = z2; }
    const int nh4 = NN * (IN_DIM / 4);
    for (int j = i; j < nh4; j += stride) {
        float4 v = reinterpret_cast<const float4*>(h)[j];
        __half2 a = __floats2half2_rn(v.x, v.y);
        __half2 b = __floats2half2_rn(v.z, v.w);
        uint2 pk;
        pk.x = *reinterpret_cast<uint32_t*>(&a);
        pk.y = *reinterpret_cast<uint32_t*>(&b);
        reinterpret_cast<uint2*>(g_h16)[j] = pk;
    }
}

// ---------------- degrees ----------------
__global__ void k_degree(const int* __restrict__ src, const int* __restrict__ dst, int n_edges) {
    int i = blockIdx.x * blockDim.x + threadIdx.x;
    int stride = gridDim.x * blockDim.x;
    for (int e = i; e < n_edges; e += stride) {
        atomicAdd(&g_norm_src[src[e]], 1.0f);
        atomicAdd(&g_norm_dst[dst[e]], 1.0f);
    }
}

__global__ void k_norm(int n_nodes) {
    int i = blockIdx.x * blockDim.x + threadIdx.x;
    if (i < n_nodes) {
        g_norm_src[i] = rsqrtf(fmaxf(g_norm_src[i], 1.0f));
        g_norm_dst[i] = rsqrtf(fmaxf(g_norm_dst[i], 1.0f));
    }
}

// ---------------- pre-split weights (transposed [n][k]) ----------------
__global__ void k_prepw(const float* __restrict__ W1, const float* __restrict__ W2) {
    int i = blockIdx.x * blockDim.x + threadIdx.x;
    const int n1 = HID_DIM * IN_DIM;
    const int n2 = OUT_DIM * HID_DIM;
    if (i < n1) {
        int n = i / IN_DIM, k = i % IN_DIM;
        float v = W1[(size_t)k * HID_DIM + n];
        __nv_bfloat16 hi, lo;
        split_bf16(v, hi, lo);
        g_w1t_hi[i] = hi; g_w1t_lo[i] = lo;
    } else if (i < n1 + n2) {
        int j = i - n1;
        int n = j / HID_DIM, k = j % HID_DIM;
        float v = W2[(size_t)k * OUT_DIM + n];
        __nv_bfloat16 hi, lo;
        split_bf16(v, hi, lo);
        g_w2t_hi[j] = hi; g_w2t_lo[j] = lo;
    }
}

// ---------------- SpMM1: xagg[dst] += h16[src]*norm_src[src], 4 edges/warp ----------------
__global__ void k_spmm1(const int* __restrict__ src, const int* __restrict__ dst,
                        int n_edges) {
    int w = (blockIdx.x * blockDim.x + threadIdx.x) >> 5;
    int lane = threadIdx.x & 31;
    int e0 = w * 4;
    if (e0 >= n_edges) return;
    int s[4], d[4];
    float ns[4];
    #pragma unroll
    for (int i = 0; i < 4; i++) {
        int e = min(e0 + i, n_edges - 1);
        s[i] = __ldg(&src[e]);
        d[i] = __ldg(&dst[e]);
    }
    #pragma unroll
    for (int i = 0; i < 4; i++) ns[i] = g_norm_src[s[i]];
    uint2 v[4];
    #pragma unroll
    for (int i = 0; i < 4; i++)
        v[i] = reinterpret_cast<const uint2*>(g_h16 + (size_t)s[i] * IN_DIM)[lane];
    #pragma unroll
    for (int i = 0; i < 4; i++) {
        if (e0 + i >= n_edges) break;
        __half2 a = *reinterpret_cast<__half2*>(&v[i].x);
        __half2 b = *reinterpret_cast<__half2*>(&v[i].y);
        float2 fa = __half22float2(a);
        float2 fb = __half22float2(b);
        float4 t;
        t.x = fa.x * ns[i]; t.y = fa.y * ns[i];
        t.z = fb.x * ns[i]; t.w = fb.y * ns[i];
        float4* orow = reinterpret_cast<float4*>(g_xagg + (size_t)d[i] * IN_DIM);
        asm volatile("red.global.add.v4.f32 [%0], {%1,%2,%3,%4};"
                     :: "l"(orow + lane), "f"(t.x), "f"(t.y), "f"(t.z), "f"(t.w)
                     : "memory");
    }
}

// ---------------- split pass: xa = split(xagg * norm_dst) ----------------
__global__ void k_split() {
    int i = blockIdx.x * blockDim.x + threadIdx.x;
    int stride = gridDim.x * blockDim.x;
    const int total = NN_PAD * (IN_DIM / 4);
    for (int j = i; j < total; j += stride) {
        int row = j >> 5;
        float nd = g_norm_dst[row];
        float4 v = reinterpret_cast<const float4*>(g_xagg)[j];
        v.x *= nd; v.y *= nd; v.z *= nd; v.w *= nd;
        __nv_bfloat16 h0, l0, h1, l1, h2, l2, h3, l3;
        split_bf16(v.x, h0, l0); split_bf16(v.y, h1, l1);
        split_bf16(v.z, h2, l2); split_bf16(v.w, h3, l3);
        uint2 ph, pl;
        __nv_bfloat162 t0(h0, h1), t1(h2, h3);
        ph.x = *reinterpret_cast<uint32_t*>(&t0);
        ph.y = *reinterpret_cast<uint32_t*>(&t1);
        __nv_bfloat162 u0(l0, l1), u1(l2, l3);
        pl.x = *reinterpret_cast<uint32_t*>(&u0);
        pl.y = *reinterpret_cast<uint32_t*>(&u1);
        reinterpret_cast<uint2*>(g_xa_hi)[j] = ph;
        reinterpret_cast<uint2*>(g_xa_lo)[j] = pl;
    }
}

// ---------------- GEMM tiles ----------------
#define BM 128
#define BN 64
#define BK 32
#define KPAD 40
// dynamic smem layout per stage (bf16 elems):
//   As_hi [BM*KPAD]=5120 @ 0
//   As_lo           @ 5120
//   Bs_hi [BN*KPAD]=2560 @ 10240
//   Bs_lo           @ 12800
#define STAGE_ELEMS 15360
#define SMEM_BYTES (2 * STAGE_ELEMS * 2)

// GEMM1: hidden = relu(xa @ W1 + b1) * clip(p,0,1); cp.async double-buffered
__global__ __launch_bounds__(256) void k_gemm1(const float* __restrict__ b1,
                                               const float* __restrict__ p,
                                               int n_nodes) {
    extern __shared__ __nv_bfloat16 smem[];
    const int m0 = blockIdx.x * BM;
    const int n0 = blockIdx.y * BN;
    const int tid = threadIdx.x;
    const int lane = tid & 31;
    const int wid = tid >> 5;
    const int warp_m = wid >> 2;
    const int warp_n = wid & 3;

    // per-thread load coordinates
    const int arow0 = tid >> 1;               // A: 2 chunks/thread/array
    const int aq0 = (tid & 1) * 2;            // q in {0,1} then {2,3} handled below
    const int bn = tid >> 2;
    const int bq = tid & 3;

    auto load_stage = [&](int s, int k0) {
        __nv_bfloat16* As_hi = smem + s * STAGE_ELEMS;
        __nv_bfloat16* As_lo = As_hi + 5120;
        __nv_bfloat16* Bs_hi = As_hi + 10240;
        __nv_bfloat16* Bs_lo = As_hi + 12800;
        // A: 512 chunks per array, 2/thread
        #pragma unroll
        for (int i = 0; i < 2; i++) {
            int idx = tid + 256 * i;
            int row = idx >> 2;
            int q = idx & 3;
            cp16(&As_hi[row * KPAD + 8 * q], &g_xa_hi[(size_t)(m0 + row) * IN_DIM + k0 + 8 * q]);
            cp16(&As_lo[row * KPAD + 8 * q], &g_xa_lo[(size_t)(m0 + row) * IN_DIM + k0 + 8 * q]);
        }
        // B: 256 chunks per array, 1/thread
        cp16(&Bs_hi[bn * KPAD + 8 * bq], &g_w1t_hi[(size_t)(n0 + bn) * IN_DIM + k0 + 8 * bq]);
        cp16(&Bs_lo[bn * KPAD + 8 * bq], &g_w1t_lo[(size_t)(n0 + bn) * IN_DIM + k0 + 8 * bq]);
        CP_COMMIT();
    };

    float acc[4][2][4];
    #pragma unroll
    for (int i = 0; i < 4; i++)
        #pragma unroll
        for (int j = 0; j < 2; j++)
            #pragma unroll
            for (int q = 0; q < 4; q++) acc[i][j][q] = 0.f;

    const int K_ITERS = IN_DIM / BK;   // 4
    load_stage(0, 0);
    for (int it = 0; it < K_ITERS; it++) {
        if (it + 1 < K_ITERS) {
            load_stage((it + 1) & 1, (it + 1) * BK);
            CP_WAIT(1);
        } else {
            CP_WAIT(0);
        }
        __syncthreads();

        __nv_bfloat16* As_hi = smem + (it & 1) * STAGE_ELEMS;
        __nv_bfloat16* As_lo = As_hi + 5120;
        __nv_bfloat16* Bs_hi = As_hi + 10240;
        __nv_bfloat16* Bs_lo = As_hi + 12800;

        #pragma unroll
        for (int ks = 0; ks < 2; ks++) {
            const int kc = ks * 16 + 2 * (lane & 3);
            uint32_t ah[4][4], al[4][4];
            #pragma unroll
            for (int i = 0; i < 4; i++) {
                int r = warp_m * 64 + i * 16 + (lane >> 2);
                ah[i][0] = *reinterpret_cast<uint32_t*>(&As_hi[r * KPAD + kc]);
                ah[i][1] = *reinterpret_cast<uint32_t*>(&As_hi[(r + 8) * KPAD + kc]);
                ah[i][2] = *reinterpret_cast<uint32_t*>(&As_hi[r * KPAD + kc + 8]);
                ah[i][3] = *reinterpret_cast<uint32_t*>(&As_hi[(r + 8) * KPAD + kc + 8]);
                al[i][0] = *reinterpret_cast<uint32_t*>(&As_lo[r * KPAD + kc]);
                al[i][1] = *reinterpret_cast<uint32_t*>(&As_lo[(r + 8) * KPAD + kc]);
                al[i][2] = *reinterpret_cast<uint32_t*>(&As_lo[r * KPAD + kc + 8]);
                al[i][3] = *reinterpret_cast<uint32_t*>(&As_lo[(r + 8) * KPAD + kc + 8]);
            }
            #pragma unroll
            for (int j = 0; j < 2; j++) {
                int c = warp_n * 16 + j * 8 + (lane >> 2);
                uint32_t bh0 = *reinterpret_cast<uint32_t*>(&Bs_hi[c * KPAD + kc]);
                uint32_t bh1 = *reinterpret_cast<uint32_t*>(&Bs_hi[c * KPAD + kc + 8]);
                uint32_t bl0 = *reinterpret_cast<uint32_t*>(&Bs_lo[c * KPAD + kc]);
                uint32_t bl1 = *reinterpret_cast<uint32_t*>(&Bs_lo[c * KPAD + kc + 8]);
                #pragma unroll
                for (int i = 0; i < 4; i++) {
                    MMA_BF16(acc[i][j], ah[i], bh0, bh1);
                    MMA_BF16(acc[i][j], ah[i], bl0, bl1);
                    MMA_BF16(acc[i][j], al[i], bh0, bh1);
                }
            }
        }
        __syncthreads();
    }

    #pragma unroll
    for (int i = 0; i < 4; i++) {
        int r = warp_m * 64 + i * 16 + (lane >> 2);
        #pragma unroll
        for (int j = 0; j < 2; j++) {
            int c0 = n0 + warp_n * 16 + j * 8 + 2 * (lane & 3);
            float bb0 = b1[c0], bb1 = b1[c0 + 1];
            float p0 = fminf(fmaxf(p[c0], 0.f), 1.f);
            float p1 = fminf(fmaxf(p[c0 + 1], 0.f), 1.f);
            #pragma unroll
            for (int hrow = 0; hrow < 2; hrow++) {
                int grow = m0 + r + 8 * hrow;
                if (grow >= n_nodes) continue;
                float v0 = fmaxf(acc[i][j][2 * hrow + 0] + bb0, 0.f) * p0;
                float v1 = fmaxf(acc[i][j][2 * hrow + 1] + bb1, 0.f) * p1;
                __nv_bfloat16 h0, l0, h1, l1;
                split_bf16(v0, h0, l0);
                split_bf16(v1, h1, l1);
                *reinterpret_cast<__nv_bfloat162*>(&g_hid_hi[(size_t)grow * HID_DIM + c0]) = __nv_bfloat162(h0, h1);
                *reinterpret_cast<__nv_bfloat162*>(&g_hid_lo[(size_t)grow * HID_DIM + c0]) = __nv_bfloat162(l0, l1);
            }
        }
    }
}

// GEMM2: ypre16 = fp16((hidden @ W2) * norm_src[row]); cp.async double-buffered
__global__ __launch_bounds__(256) void k_gemm2(int n_nodes) {
    extern __shared__ __nv_bfloat16 smem[];
    const int m0 = blockIdx.x * BM;
    const int tid = threadIdx.x;
    const int lane = tid & 31;
    const int wid = tid >> 5;
    const int warp_m = wid >> 2;
    const int warp_n = wid & 3;

    const int bn = tid >> 2;
    const int bq = tid & 3;

    auto load_stage = [&](int s, int k0) {
        __nv_bfloat16* As_hi = smem + s * STAGE_ELEMS;
        __nv_bfloat16* As_lo = As_hi + 5120;
        __nv_bfloat16* Bs_hi = As_hi + 10240;
        __nv_bfloat16* Bs_lo = As_hi + 12800;
        #pragma unroll
        for (int i = 0; i < 2; i++) {
            int idx = tid + 256 * i;
            int row = idx >> 2;
            int q = idx & 3;
            cp16(&As_hi[row * KPAD + 8 * q], &g_hid_hi[(size_t)(m0 + row) * HID_DIM + k0 + 8 * q]);
            cp16(&As_lo[row * KPAD + 8 * q], &g_hid_lo[(size_t)(m0 + row) * HID_DIM + k0 + 8 * q]);
        }
        cp16(&Bs_hi[bn * KPAD + 8 * bq], &g_w2t_hi[(size_t)bn * HID_DIM + k0 + 8 * bq]);
        cp16(&Bs_lo[bn * KPAD + 8 * bq], &g_w2t_lo[(size_t)bn * HID_DIM + k0 + 8 * bq]);
        CP_COMMIT();
    };

    float acc[4][2][4];
    #pragma unroll
    for (int i = 0; i < 4; i++)
        #pragma unroll
        for (int j = 0; j < 2; j++)
            #pragma unroll
            for (int q = 0; q < 4; q++) acc[i][j][q] = 0.f;

    const int K_ITERS = HID_DIM / BK;   // 8
    load_stage(0, 0);
    for (int it = 0; it < K_ITERS; it++) {
        if (it + 1 < K_ITERS) {
            load_stage((it + 1) & 1, (it + 1) * BK);
            CP_WAIT(1);
        } else {
            CP_WAIT(0);
        }
        __syncthreads();

        __nv_bfloat16* As_hi = smem + (it & 1) * STAGE_ELEMS;
        __nv_bfloat16* As_lo = As_hi + 5120;
        __nv_bfloat16* Bs_hi = As_hi + 10240;
        __nv_bfloat16* Bs_lo = As_hi + 12800;

        #pragma unroll
        for (int ks = 0; ks < 2; ks++) {
            const int kc = ks * 16 + 2 * (lane & 3);
            uint32_t ah[4][4], al[4][4];
            #pragma unroll
            for (int i = 0; i < 4; i++) {
                int r = warp_m * 64 + i * 16 + (lane >> 2);
                ah[i][0] = *reinterpret_cast<uint32_t*>(&As_hi[r * KPAD + kc]);
                ah[i][1] = *reinterpret_cast<uint32_t*>(&As_hi[(r + 8) * KPAD + kc]);
                ah[i][2] = *reinterpret_cast<uint32_t*>(&As_hi[r * KPAD + kc + 8]);
                ah[i][3] = *reinterpret_cast<uint32_t*>(&As_hi[(r + 8) * KPAD + kc + 8]);
                al[i][0] = *reinterpret_cast<uint32_t*>(&As_lo[r * KPAD + kc]);
                al[i][1] = *reinterpret_cast<uint32_t*>(&As_lo[(r + 8) * KPAD + kc]);
                al[i][2] = *reinterpret_cast<uint32_t*>(&As_lo[r * KPAD + kc + 8]);
                al[i][3] = *reinterpret_cast<uint32_t*>(&As_lo[(r + 8) * KPAD + kc + 8]);
            }
            #pragma unroll
            for (int j = 0; j < 2; j++) {
                int c = warp_n * 16 + j * 8 + (lane >> 2);
                uint32_t bh0 = *reinterpret_cast<uint32_t*>(&Bs_hi[c * KPAD + kc]);
                uint32_t bh1 = *reinterpret_cast<uint32_t*>(&Bs_hi[c * KPAD + kc + 8]);
                uint32_t bl0 = *reinterpret_cast<uint32_t*>(&Bs_lo[c * KPAD + kc]);
                uint32_t bl1 = *reinterpret_cast<uint32_t*>(&Bs_lo[c * KPAD + kc + 8]);
                #pragma unroll
                for (int i = 0; i < 4; i++) {
                    MMA_BF16(acc[i][j], ah[i], bh0, bh1);
                    MMA_BF16(acc[i][j], ah[i], bl0, bl1);
                    MMA_BF16(acc[i][j], al[i], bh0, bh1);
                }
            }
        }
        __syncthreads();
    }

    #pragma unroll
    for (int i = 0; i < 4; i++) {
        int r = warp_m * 64 + i * 16 + (lane >> 2);
        #pragma unroll
        for (int j = 0; j < 2; j++) {
            int c0 = warp_n * 16 + j * 8 + 2 * (lane & 3);
            #pragma unroll
            for (int hrow = 0; hrow < 2; hrow++) {
                int grow = m0 + r + 8 * hrow;
                if (grow >= n_nodes) continue;
                float ns = g_norm_src[grow];
                __half2 v = __floats2half2_rn(acc[i][j][2 * hrow + 0] * ns,
                                              acc[i][j][2 * hrow + 1] * ns);
                *reinterpret_cast<__half2*>(&g_ypre16[(size_t)grow * OUT_DIM + c0]) = v;
            }
        }
    }
}

// ---------------- SpMM2 (fused final): out[dst] += ypre16[src]*norm_dst[dst] ----------------
__global__ void k_spmm2(const int* __restrict__ src, const int* __restrict__ dst,
                        float* __restrict__ out, int n_edges) {
    int w = (blockIdx.x * blockDim.x + threadIdx.x) >> 5;
    int lane = threadIdx.x & 31;
    int half = lane >> 4;
    int l = lane & 15;
    int e0 = w * 8;
    if (e0 >= n_edges) return;
    int s[4], d[4];
    #pragma unroll
    for (int i = 0; i < 4; i++) {
        int e = min(e0 + 2 * i + half, n_edges - 1);
        s[i] = __ldg(&src[e]);
        d[i] = __ldg(&dst[e]);
    }
    float nd[4];
    #pragma unroll
    for (int i = 0; i < 4; i++) nd[i] = g_norm_dst[d[i]];
    uint2 v[4];
    #pragma unroll
    for (int i = 0; i < 4; i++)
        v[i] = reinterpret_cast<const uint2*>(g_ypre16 + (size_t)s[i] * OUT_DIM)[l];
    #pragma unroll
    for (int i = 0; i < 4; i++) {
        if (e0 + 2 * i + half >= n_edges) break;
        __half2 a = *reinterpret_cast<__half2*>(&v[i].x);
        __half2 b = *reinterpret_cast<__half2*>(&v[i].y);
        float2 fa = __half22float2(a);
        float2 fb = __half22float2(b);
        float4 t;
        t.x = fa.x * nd[i]; t.y = fa.y * nd[i];
        t.z = fb.x * nd[i]; t.w = fb.y * nd[i];
        float4* orow = reinterpret_cast<float4*>(out + (size_t)d[i] * OUT_DIM);
        asm volatile("red.global.add.v4.f32 [%0], {%1,%2,%3,%4};"
                     :: "l"(orow + l), "f"(t.x), "f"(t.y), "f"(t.z), "f"(t.w)
                     : "memory");
    }
}

// ---------------- launch ----------------
extern "C" void kernel_launch(void* const* d_in, const int* in_sizes, int n_in,
                              void* d_out, int out_size) {
    const float* h  = (const float*)d_in[0];
    const float* W1 = (const float*)d_in[1];
    const float* b1 = (const float*)d_in[2];
    const float* W2 = (const float*)d_in[3];
    const float* b2 = (const float*)d_in[4];
    const float* p  = (const float*)d_in[5];
    const int* src  = (const int*)d_in[6];
    const int* dst  = (const int*)d_in[7];

    const int n_nodes = in_sizes[0] / IN_DIM;   // 100000
    const int n_edges = in_sizes[6];            // 1600000
    float* out = (float*)d_out;

    cudaFuncSetAttribute(k_gemm1, cudaFuncAttributeMaxDynamicSharedMemorySize, SMEM_BYTES);
    cudaFuncSetAttribute(k_gemm2, cudaFuncAttributeMaxDynamicSharedMemorySize, SMEM_BYTES);

    k_zero<<<4096, 256>>>(h, b2, reinterpret_cast<float4*>(out), n_nodes);
    k_prepw<<<(HID_DIM * IN_DIM + OUT_DIM * HID_DIM + 255) / 256, 256>>>(W1, W2);
    k_degree<<<(n_edges + 255) / 256, 256>>>(src, dst, n_edges);
    k_norm<<<(n_nodes + 255) / 256, 256>>>(n_nodes);

    {
        int warps = (n_edges + 3) / 4;
        k_spmm1<<<(warps + 7) / 8, 256>>>(src, dst, n_edges);
    }
    k_split<<<2048, 256>>>();
    {
        dim3 grid(NN_PAD / BM, HID_DIM / BN);   // 782 x 4
        k_gemm1<<<grid, 256, SMEM_BYTES>>>(b1, p, n_nodes);
    }
    {
        dim3 grid(NN_PAD / BM, 1);              // 782
        k_gemm2<<<grid, 256, SMEM_BYTES>>>(n_nodes);
    }
    {
        int warps = (n_edges + 7) / 8;
        k_spmm2<<<(warps + 7) / 8, 256>>>(src, dst, out, n_edges);
    }
}